// round 12
// baseline (speedup 1.0000x reference)
#include <cuda_runtime.h>
#include <math.h>

#define BB 64
#define TT 1024
#define II 512
#define HH 1024
#define GG (4*HH)   // 4096
#define TOPN 256
#define NCTA 128
#define NTHR 512

// Dynamic smem carve for k_rec
#define SM_WS_BYTES (1024*36*4)          // ws[1024][36] = 147456 (Wh slice; 16B rows)
#define SM_GRP_BYTES (2*16*68*4)         // per group: 2 h-chunk slots 16x68 = 8704
#define SM_REC_TOTAL (SM_WS_BYTES + 8*SM_GRP_BYTES)   // 217088 (proven OK)
// ps[g][32][68] (8704 B) aliases group g's two h slots after its GEMM finishes.

// Scratch (allocation-free rule: __device__ globals)
__device__ __align__(16) float g_xg[(size_t)BB*TT*GG];   // 1 GiB: x@Wi^T + bi
__device__ __align__(16) float g_hb[2][BB*HH];           // double-buffered h
__device__ unsigned g_bar_count = 0;
__device__ volatile unsigned g_bar_gen = 0;

// Packed fp32x2 FMA (Blackwell): d = a*b + d per 32-bit half.
__device__ __forceinline__ float2 ffma2(float2 d, float2 a, float2 b) {
    asm("fma.rn.f32x2 %0, %1, %2, %0;"
        : "+l"(reinterpret_cast<unsigned long long&>(d))
        : "l"(reinterpret_cast<unsigned long long&>(a)),
          "l"(reinterpret_cast<unsigned long long&>(b)));
    return d;
}

// Group-scoped named barrier (64 threads of k-split group g)
__device__ __forceinline__ void barg(int g) {
    asm volatile("bar.sync %0, %1;" :: "r"(g + 1), "r"(64) : "memory");
}

// ---------------------------------------------------------------- xg = x @ Wi^T + bi
__global__ void __launch_bounds__(256) k_xg(const float* __restrict__ x,
                                            const float* __restrict__ Wi,
                                            const float* __restrict__ bi) {
    __shared__ float  xs[16][132];
    __shared__ float2 ws2[16][130];
    int m0 = blockIdx.y * 128;
    int n0 = blockIdx.x * 128;
    int tid = threadIdx.x;
    int tr = tid >> 4;
    int tc = tid & 15;
    float2 acc2[4][8];
#pragma unroll
    for (int p = 0; p < 4; p++)
#pragma unroll
        for (int v = 0; v < 8; v++) acc2[p][v] = make_float2(0.f, 0.f);

    for (int k0 = 0; k0 < II; k0 += 16) {
#pragma unroll
        for (int i = 0; i < 8; i++) {
            int lin = tid + i*256;
            int r = lin >> 4, kk = lin & 15;
            xs[kk][r] = x[(size_t)(m0 + r)*II + k0 + kk];
            float w = Wi[(size_t)(n0 + r)*II + k0 + kk];
            ws2[kk][r] = make_float2(w, w);
        }
        __syncthreads();
#pragma unroll
        for (int kk = 0; kk < 16; kk++) {
            float4 aA = *(const float4*)&xs[kk][tr*4];
            float4 aB = *(const float4*)&xs[kk][64 + tr*4];
            float2 ap[4] = { make_float2(aA.x, aA.y), make_float2(aA.z, aA.w),
                             make_float2(aB.x, aB.y), make_float2(aB.z, aB.w) };
            float4 wA = *(const float4*)&ws2[kk][tc*4];
            float4 wB = *(const float4*)&ws2[kk][tc*4 + 2];
            float4 wC = *(const float4*)&ws2[kk][64 + tc*4];
            float4 wD = *(const float4*)&ws2[kk][64 + tc*4 + 2];
            float2 wd[8] = { make_float2(wA.x, wA.y), make_float2(wA.z, wA.w),
                             make_float2(wB.x, wB.y), make_float2(wB.z, wB.w),
                             make_float2(wC.x, wC.y), make_float2(wC.z, wC.w),
                             make_float2(wD.x, wD.y), make_float2(wD.z, wD.w) };
#pragma unroll
            for (int p = 0; p < 4; p++)
#pragma unroll
                for (int v = 0; v < 8; v++)
                    acc2[p][v] = ffma2(acc2[p][v], ap[p], wd[v]);
        }
        __syncthreads();
    }
    float bv[8];
#pragma unroll
    for (int v = 0; v < 8; v++) {
        int n = n0 + ((v < 4) ? (tc*4 + v) : (64 + tc*4 + v - 4));
        bv[v] = bi[n];
    }
#pragma unroll
    for (int p = 0; p < 4; p++) {
        int m = m0 + ((p < 2) ? (tr*4 + 2*p) : (64 + tr*4 + 2*(p - 2)));
#pragma unroll
        for (int v = 0; v < 8; v++) {
            int n = n0 + ((v < 4) ? (tc*4 + v) : (64 + tc*4 + v - 4));
            g_xg[(size_t)m*GG + n]       = acc2[p][v].x + bv[v];
            g_xg[(size_t)(m+1)*GG + n]   = acc2[p][v].y + bv[v];
        }
    }
}

// ---------------------------------------------------------------- grid barrier
__device__ __forceinline__ void grid_bar() {
    __syncthreads();
    if (threadIdx.x == 0) {
        __threadfence();
        unsigned gen = g_bar_gen;
        if (atomicAdd(&g_bar_count, 1u) == NCTA - 1) {
            g_bar_count = 0;
            __threadfence();
            g_bar_gen = gen + 1;
        } else {
            while (g_bar_gen == gen) __nanosleep(16);
            __threadfence();
        }
    }
    __syncthreads();
}

// ---------------------------------------------------------------- persistent recurrence
// 128 CTAs x 512 thr (16 warps -> 4/SMSP). CTA owns 8 h-cols (32 gate rows).
// K-split x8 via 64-thread groups (K=128 each); thread tile 8m x 4n, f32x2
// over m-pairs. Group-private double-buffered h chunks; named group barriers.
// ps[g] aliases group g's h slots (dead after its GEMM).
__global__ void __launch_bounds__(NTHR) k_rec(const float* __restrict__ Wh,
                                              const float* __restrict__ bh,
                                              const float* __restrict__ h0,
                                              const float* __restrict__ c0,
                                              const float* __restrict__ topic,
                                              const float* __restrict__ Wt,
                                              const float* __restrict__ bt,
                                              float* __restrict__ out) {
    extern __shared__ char smraw[];
    float (*ws)[36] = (float(*)[36])smraw;            // [k][nl] Wh slice
    char* grp = smraw + SM_WS_BYTES;                  // 8 x 8704 group regions

    const int tid  = threadIdx.x;
    const int c    = blockIdx.x;
    const int j0   = c * 8;
    const int g    = tid >> 6;                 // k-split group 0..7
    const int lane = tid & 63;
    const int m0   = (lane & 7) * 8;           // 8 m-values
    const int m0h  = m0 + (m0 >> 5) * 4;       // holed compute index (16B aligned)
    const int nl0  = (lane >> 3) * 4;          // 4 n-values
    const int kb0  = g * 128;                  // group K-range [kb0, kb0+128)
    const int ml   = lane;                     // loader batch row 0..63
    const int mIdx = ml + (ml >> 5) * 4;       // holed store index

    float (*hsA)[68] = (float(*)[68])(grp + g*SM_GRP_BYTES);          // slot 0
    float (*hsB)[68] = (float(*)[68])(grp + g*SM_GRP_BYTES + 16*68*4);// slot 1

    // ---- stage h0 slice
    g_hb[0][c*512 + tid] = h0[c*512 + tid];

    // ---- upload Wh slice -> ws[k][nl] (scalar, transposed)
    {
        const int nl = tid >> 4;          // 0..31
        const int kq = tid & 15;          // 0..15
        const float* wr = Wh + (size_t)((nl >> 3)*HH + j0 + (nl & 7)) * HH;
#pragma unroll 4
        for (int i = 0; i < 16; i++) {
            int k = i*64 + kq*4;
            float4 w4 = __ldg((const float4*)(wr + k));
            ws[k  ][nl] = w4.x;
            ws[k+1][nl] = w4.y;
            ws[k+2][nl] = w4.z;
            ws[k+3][nl] = w4.w;
        }
    }

    // ---- elementwise constants (1 cell per thread)
    const int b_e = tid >> 3;             // 0..63
    const int j_e = tid & 7;              // 0..7
    const int jg  = j0 + j_e;
    float cr = c0[b_e*HH + jg];
    float tg = bt[jg];
    {
        const float* tp = topic + b_e*TOPN;
        const float* wt = Wt + (size_t)jg * TOPN;
#pragma unroll 8
        for (int k = 0; k < TOPN; k++)
            tg += __ldg(tp + k) * __ldg(wt + k);
    }
    float bhv[4];
#pragma unroll
    for (int gt = 0; gt < 4; gt++) bhv[gt] = bh[gt*HH + jg];

    grid_bar();   // h0 + ws of all CTAs ready

    for (int t = 0; t < TT; t++) {
        const int rb = t & 1, wb = rb ^ 1;
        const float* hbase = g_hb[rb];

        // xg prefetch for elementwise (overlaps whole GEMM)
        const size_t xb = ((size_t)b_e*TT + t)*GG + jg;
        float x_i = __ldcs(&g_xg[xb]);
        float x_f = __ldcs(&g_xg[xb + HH]);
        float x_c = __ldcs(&g_xg[xb + 2*(size_t)HH]);
        float x_o = __ldcs(&g_xg[xb + 3*(size_t)HH]);

        float2 acc[4][4];    // [j = n offset][p = m pair]
#pragma unroll
        for (int j = 0; j < 4; j++)
#pragma unroll
            for (int p = 0; p < 4; p++) acc[j][p] = make_float2(0.f, 0.f);

        const float* hrow = hbase + ml*HH + kb0;   // this thread's m-row, group K range
        float4 pf0, pf1, pf2, pf3;

        // prologue: chunk 0 -> slot A
        pf0 = __ldcg((const float4*)(hrow));
        pf1 = __ldcg((const float4*)(hrow + 4));
        pf2 = __ldcg((const float4*)(hrow + 8));
        pf3 = __ldcg((const float4*)(hrow + 12));
        hsA[ 0][mIdx]=pf0.x; hsA[ 1][mIdx]=pf0.y; hsA[ 2][mIdx]=pf0.z; hsA[ 3][mIdx]=pf0.w;
        hsA[ 4][mIdx]=pf1.x; hsA[ 5][mIdx]=pf1.y; hsA[ 6][mIdx]=pf1.z; hsA[ 7][mIdx]=pf1.w;
        hsA[ 8][mIdx]=pf2.x; hsA[ 9][mIdx]=pf2.y; hsA[10][mIdx]=pf2.z; hsA[11][mIdx]=pf2.w;
        hsA[12][mIdx]=pf3.x; hsA[13][mIdx]=pf3.y; hsA[14][mIdx]=pf3.z; hsA[15][mIdx]=pf3.w;
        barg(g);

        for (int cc = 0; cc < 8; cc++) {
            float (*cur)[68] = (cc & 1) ? hsB : hsA;
            float (*nxt)[68] = (cc & 1) ? hsA : hsB;
            const bool more = (cc < 7);
            if (more) {
                const float* q = hrow + (cc + 1)*16;
                pf0 = __ldcg((const float4*)(q));
                pf1 = __ldcg((const float4*)(q + 4));
                pf2 = __ldcg((const float4*)(q + 8));
                pf3 = __ldcg((const float4*)(q + 12));
            }
            const int kb = kb0 + cc*16;
#pragma unroll
            for (int kk = 0; kk < 16; kk++) {
                float4 h01 = *(const float4*)&cur[kk][m0h];
                float4 h23 = *(const float4*)&cur[kk][m0h + 4];
                float4 wv  = *(const float4*)&ws[kb + kk][nl0];
                float2 hp[4] = { make_float2(h01.x, h01.y), make_float2(h01.z, h01.w),
                                 make_float2(h23.x, h23.y), make_float2(h23.z, h23.w) };
                float wa[4] = { wv.x, wv.y, wv.z, wv.w };
#pragma unroll
                for (int j = 0; j < 4; j++) {
                    float2 wd = make_float2(wa[j], wa[j]);
#pragma unroll
                    for (int p = 0; p < 4; p++)
                        acc[j][p] = ffma2(acc[j][p], hp[p], wd);
                }
            }
            if (more) {
                nxt[ 0][mIdx]=pf0.x; nxt[ 1][mIdx]=pf0.y; nxt[ 2][mIdx]=pf0.z; nxt[ 3][mIdx]=pf0.w;
                nxt[ 4][mIdx]=pf1.x; nxt[ 5][mIdx]=pf1.y; nxt[ 6][mIdx]=pf1.z; nxt[ 7][mIdx]=pf1.w;
                nxt[ 8][mIdx]=pf2.x; nxt[ 9][mIdx]=pf2.y; nxt[10][mIdx]=pf2.z; nxt[11][mIdx]=pf2.w;
                nxt[12][mIdx]=pf3.x; nxt[13][mIdx]=pf3.y; nxt[14][mIdx]=pf3.z; nxt[15][mIdx]=pf3.w;
            }
            barg(g);
        }

        // write K-split partials into this group's region (h slots now dead)
        {
            float (*psg)[68] = (float(*)[68])(grp + g*SM_GRP_BYTES);
#pragma unroll
            for (int j = 0; j < 4; j++) {
                int n = nl0 + j;
                *(float4*)&psg[n][m0]     = make_float4(acc[j][0].x, acc[j][0].y, acc[j][1].x, acc[j][1].y);
                *(float4*)&psg[n][m0 + 4] = make_float4(acc[j][2].x, acc[j][2].y, acc[j][3].x, acc[j][3].y);
            }
        }
        __syncthreads();

        // elementwise for the 1 owned cell (sum 8 k-split partials per gate)
        {
            float s[4];
#pragma unroll
            for (int gt = 0; gt < 4; gt++) {
                int n = gt*8 + j_e;
                float acc_s = 0.f;
#pragma unroll
                for (int gg = 0; gg < 8; gg++) {
                    float (*psg)[68] = (float(*)[68])(grp + gg*SM_GRP_BYTES);
                    acc_s += psg[n][b_e];
                }
                s[gt] = acc_s;
            }
            float gi = s[0] + x_i + bhv[0] + tg;
            float gf = s[1] + x_f + bhv[1] + tg;
            float gc = s[2] + x_c + bhv[2];
            float go = s[3] + x_o + bhv[3];

            float ig = 1.f/(1.f + expf(-gi));
            float fg = 1.f/(1.f + expf(-gf));
            float cg = tanhf(gc);
            float og = 1.f/(1.f + expf(-go));
            float cy = fg*cr + ig*cg;
            float hy = og * tanhf(cy);
            cr = cy;

            g_hb[wb][b_e*HH + jg] = hy;
            out[((size_t)b_e*TT + t)*HH + jg] = hy;
            if (t == TT - 1) {
                const size_t HN = (size_t)BB*TT*HH;
                out[HN + b_e*HH + jg]                 = hy;
                out[HN + (size_t)BB*HH + b_e*HH + jg] = cy;
            }
        }
        if (t < TT - 1) grid_bar();
    }
}

// ----------------------------------------------------------------
extern "C" void kernel_launch(void* const* d_in, const int* in_sizes, int n_in,
                              void* d_out, int out_size) {
    const float* x     = (const float*)d_in[0];
    const float* h0    = (const float*)d_in[1];
    const float* c0    = (const float*)d_in[2];
    const float* topic = (const float*)d_in[3];
    const float* Wi    = (const float*)d_in[4];
    const float* bi    = (const float*)d_in[5];
    const float* Wh    = (const float*)d_in[6];
    const float* bh    = (const float*)d_in[7];
    const float* Wt    = (const float*)d_in[8];
    const float* bt    = (const float*)d_in[9];
    float* out = (float*)d_out;

    cudaFuncSetAttribute(k_rec, cudaFuncAttributeMaxDynamicSharedMemorySize, SM_REC_TOTAL);

    k_xg<<<dim3(GG/128, (BB*TT)/128), 256>>>(x, Wi, bi);   // (32, 512)
    k_rec<<<NCTA, NTHR, SM_REC_TOTAL>>>(Wh, bh, h0, c0, topic, Wt, bt, out);
}

// round 15
// speedup vs baseline: 1.1747x; 1.1747x over previous
#include <cuda_runtime.h>
#include <cuda_bf16.h>
#include <cstdint>
#include <stdint.h>
#include <math.h>

#define BB 64
#define TT 1024
#define II 512
#define HH 1024
#define GG (4*HH)
#define TOPN 256
#define NCTA 128
#define NTHR 256

// ---- smem carve for k_rec ----
// A staging: 8 warps x 2 bufs x 2 terms x (32 rows x 80B) = 81920
#define SM_A      0
#define A_TERM    2560
#define A_BUF     5120
#define A_WARP    10240
// W resident: [32][1024] bf16, row stride 2064 B (516 words, mod32=4 -> conflict-free B frags)
#define WSTRIDE   2064
#define SM_W0     81920
#define SM_W1     (SM_W0 + 32*WSTRIDE)          // 147968
#define SM_TOTAL  (SM_W1 + 32*WSTRIDE)          // 214016
// ps[4][64][33] fp32 = 33792 aliases SM_A after GEMM

// ---- device globals (allocation-free scratch) ----
__device__ __align__(16) float g_xg[(size_t)BB*TT*GG];        // 1 GiB: x@Wi^T + bi
__device__ __align__(16) __nv_bfloat16 g_hv[2][2][BB*HH];     // h double-buffer x {hi,lo}
__device__ unsigned g_bar_count = 0;
__device__ volatile unsigned g_bar_gen = 0;

// ---------------------------------------------------------------- helpers
__device__ __forceinline__ uint32_t smem_u32(const void* p) {
    uint32_t a;
    asm("{ .reg .u64 t; cvta.to.shared.u64 t, %1; cvt.u32.u64 %0, t; }" : "=r"(a) : "l"(p));
    return a;
}
__device__ __forceinline__ void ldm4(uint32_t* r, uint32_t addr) {
    asm volatile("ldmatrix.sync.aligned.m8n8.x4.shared.b16 {%0,%1,%2,%3}, [%4];"
        : "=r"(r[0]), "=r"(r[1]), "=r"(r[2]), "=r"(r[3]) : "r"(addr));
}
__device__ __forceinline__ uint32_t lds32(uint32_t addr) {
    uint32_t v;
    asm volatile("ld.shared.b32 %0, [%1];" : "=r"(v) : "r"(addr));
    return v;
}
__device__ __forceinline__ void mma16816(float* c, const uint32_t* a, uint32_t b0, uint32_t b1) {
    asm volatile("mma.sync.aligned.m16n8k16.row.col.f32.bf16.bf16.f32 "
        "{%0,%1,%2,%3}, {%4,%5,%6,%7}, {%8,%9}, {%0,%1,%2,%3};"
        : "+f"(c[0]), "+f"(c[1]), "+f"(c[2]), "+f"(c[3])
        : "r"(a[0]), "r"(a[1]), "r"(a[2]), "r"(a[3]), "r"(b0), "r"(b1));
}
__device__ __forceinline__ uint32_t pack_bf2(__nv_bfloat16 a, __nv_bfloat16 b) {
    __nv_bfloat162 t = __halves2bfloat162(a, b);
    return *reinterpret_cast<uint32_t*>(&t);
}
__device__ __forceinline__ float2 ffma2(float2 d, float2 a, float2 b) {
    asm("fma.rn.f32x2 %0, %1, %2, %0;"
        : "+l"(reinterpret_cast<unsigned long long&>(d))
        : "l"(reinterpret_cast<unsigned long long&>(a)),
          "l"(reinterpret_cast<unsigned long long&>(b)));
    return d;
}

// ---------------------------------------------------------------- xg = x @ Wi^T + bi (fp32 SIMT, proven)
__global__ void __launch_bounds__(256) k_xg(const float* __restrict__ x,
                                            const float* __restrict__ Wi,
                                            const float* __restrict__ bi) {
    __shared__ float  xs[16][132];
    __shared__ float2 ws2[16][130];
    int m0 = blockIdx.y * 128;
    int n0 = blockIdx.x * 128;
    int tid = threadIdx.x;
    int tr = tid >> 4;
    int tc = tid & 15;
    float2 acc2[4][8];
#pragma unroll
    for (int p = 0; p < 4; p++)
#pragma unroll
        for (int v = 0; v < 8; v++) acc2[p][v] = make_float2(0.f, 0.f);

    for (int k0 = 0; k0 < II; k0 += 16) {
#pragma unroll
        for (int i = 0; i < 8; i++) {
            int lin = tid + i*256;
            int r = lin >> 4, kk = lin & 15;
            xs[kk][r] = x[(size_t)(m0 + r)*II + k0 + kk];
            float w = Wi[(size_t)(n0 + r)*II + k0 + kk];
            ws2[kk][r] = make_float2(w, w);
        }
        __syncthreads();
#pragma unroll
        for (int kk = 0; kk < 16; kk++) {
            float4 aA = *(const float4*)&xs[kk][tr*4];
            float4 aB = *(const float4*)&xs[kk][64 + tr*4];
            float2 ap[4] = { make_float2(aA.x, aA.y), make_float2(aA.z, aA.w),
                             make_float2(aB.x, aB.y), make_float2(aB.z, aB.w) };
            float4 wA = *(const float4*)&ws2[kk][tc*4];
            float4 wB = *(const float4*)&ws2[kk][tc*4 + 2];
            float4 wC = *(const float4*)&ws2[kk][64 + tc*4];
            float4 wD = *(const float4*)&ws2[kk][64 + tc*4 + 2];
            float2 wd[8] = { make_float2(wA.x, wA.y), make_float2(wA.z, wA.w),
                             make_float2(wB.x, wB.y), make_float2(wB.z, wB.w),
                             make_float2(wC.x, wC.y), make_float2(wC.z, wC.w),
                             make_float2(wD.x, wD.y), make_float2(wD.z, wD.w) };
#pragma unroll
            for (int p = 0; p < 4; p++)
#pragma unroll
                for (int v = 0; v < 8; v++)
                    acc2[p][v] = ffma2(acc2[p][v], ap[p], wd[v]);
        }
        __syncthreads();
    }
    float bv[8];
#pragma unroll
    for (int v = 0; v < 8; v++) {
        int n = n0 + ((v < 4) ? (tc*4 + v) : (64 + tc*4 + v - 4));
        bv[v] = bi[n];
    }
#pragma unroll
    for (int p = 0; p < 4; p++) {
        int m = m0 + ((p < 2) ? (tr*4 + 2*p) : (64 + tr*4 + 2*(p - 2)));
#pragma unroll
        for (int v = 0; v < 8; v++) {
            int n = n0 + ((v < 4) ? (tc*4 + v) : (64 + tc*4 + v - 4));
            g_xg[(size_t)m*GG + n]       = acc2[p][v].x + bv[v];
            g_xg[(size_t)(m+1)*GG + n]   = acc2[p][v].y + bv[v];
        }
    }
}

// ---------------------------------------------------------------- grid barrier
__device__ __forceinline__ void grid_bar() {
    __syncthreads();
    if (threadIdx.x == 0) {
        __threadfence();
        unsigned gen = g_bar_gen;
        if (atomicAdd(&g_bar_count, 1u) == NCTA - 1) {
            g_bar_count = 0;
            __threadfence();
            g_bar_gen = gen + 1;
        } else {
            while (g_bar_gen == gen) __nanosleep(16);
            __threadfence();
        }
    }
    __syncthreads();
}

// ---------------------------------------------------------------- persistent recurrence (mma.sync HMMA)
// 128 CTAs x 256 thr. CTA c: 32 gate rows (n), 64 batches (m), K=1024.
// Warp w = (m-half mh, k-quarter kq): tile 32m x 32n x 256k; acc 2x4 mma tiles.
// W resident bf16 hi/lo [32][1024] (stride 2064B). h streamed per-warp in
// double-buffered [32x32] bf16 chunks (stride 80B, ldmatrix-conflict-free).
// 3-term split A0B0 + A0B1 + A1B0, fp32 accum. ps[4][64][33] aliases A region.
__global__ void __launch_bounds__(NTHR)
k_rec(const float* __restrict__ Wh, const float* __restrict__ bh,
      const float* __restrict__ h0, const float* __restrict__ c0,
      const float* __restrict__ topic, const float* __restrict__ Wt,
      const float* __restrict__ bt, float* __restrict__ out) {
    extern __shared__ char sm[];
    const uint32_t smb = smem_u32(sm);
    const int tid  = threadIdx.x;
    const int c    = blockIdx.x;
    const int j0   = c * 8;
    const int w    = tid >> 5;
    const int lane = tid & 31;
    const int mh   = w >> 2;          // m-half 0..1
    const int kq   = w & 3;           // k-quarter 0..3

    // ---- upload W slice -> hi/lo bf16, [n][k] rows of 2064 B
    {
        const int nl = tid >> 3;          // 0..31
        const int kb = tid & 7;           // 0..7
        const float* wr = Wh + (size_t)((nl >> 3)*HH + j0 + (nl & 7)) * HH;
        char* w0p = sm + SM_W0 + nl*WSTRIDE;
        char* w1p = sm + SM_W1 + nl*WSTRIDE;
        for (int i = 0; i < 32; i++) {
            int k = i*32 + kb*4;
            float4 w4 = __ldg((const float4*)(wr + k));
            float v[4] = {w4.x, w4.y, w4.z, w4.w};
            __nv_bfloat16 hi[4], lo[4];
#pragma unroll
            for (int e = 0; e < 4; e++) {
                hi[e] = __float2bfloat16(v[e]);
                lo[e] = __float2bfloat16(v[e] - __bfloat162float(hi[e]));
            }
            *(uint2*)(w0p + k*2) = make_uint2(pack_bf2(hi[0],hi[1]), pack_bf2(hi[2],hi[3]));
            *(uint2*)(w1p + k*2) = make_uint2(pack_bf2(lo[0],lo[1]), pack_bf2(lo[2],lo[3]));
        }
    }

    // ---- h0 -> hi/lo bf16 global (2 elements per thread)
#pragma unroll
    for (int i = 0; i < 2; i++) {
        int idx = c*512 + tid + i*256;
        float v = h0[idx];
        __nv_bfloat16 hi = __float2bfloat16(v);
        g_hv[0][0][idx] = hi;
        g_hv[0][1][idx] = __float2bfloat16(v - __bfloat162float(hi));
    }

    // ---- elementwise constants (2 cells per thread: (b_e, jg0), (b_e, jg0+1))
    const int b_e  = tid >> 2;
    const int jl_e = (tid & 3) * 2;
    const int jg0  = j0 + jl_e;
    float cr0 = c0[b_e*HH + jg0];
    float cr1 = c0[b_e*HH + jg0 + 1];
    float tg0 = bt[jg0], tg1 = bt[jg0 + 1];
    {
        const float* tp  = topic + b_e*TOPN;
        const float* wt0 = Wt + (size_t)jg0 * TOPN;
        const float* wt1 = Wt + (size_t)(jg0 + 1) * TOPN;
#pragma unroll 8
        for (int k = 0; k < TOPN; k++) {
            float tv = __ldg(tp + k);
            tg0 += tv * __ldg(wt0 + k);
            tg1 += tv * __ldg(wt1 + k);
        }
    }
    float bhv[4][2];
#pragma unroll
    for (int gt = 0; gt < 4; gt++) {
        bhv[gt][0] = bh[gt*HH + jg0];
        bhv[gt][1] = bh[gt*HH + jg0 + 1];
    }

    // ---- per-lane address precompute
    const uint32_t aW = smb + SM_A + w*A_WARP;                       // this warp's A region
    const uint32_t lmoff = (uint32_t)((lane & 15)*80 + (lane >> 4)*16); // ldmatrix lane offset
    // B fragment base (bytes into W region, before k offset): n = nt*8 + (lane>>2), kpair byte = (lane&3)*4
    uint32_t bOff[4];
#pragma unroll
    for (int nt = 0; nt < 4; nt++)
        bOff[nt] = (uint32_t)((nt*8 + (lane >> 2))*WSTRIDE + (lane & 3)*4);
    const int gmRow = mh*32 + lane;    // staged h row (this lane loads one row/chunk/term)

    grid_bar();   // h0 + W of all CTAs ready

    for (int t = 0; t < TT; t++) {
        const int rb = t & 1, wb = rb ^ 1;

        // xg prefetch (overlaps whole GEMM)
        const size_t xb = ((size_t)b_e*TT + t)*GG + jg0;
        float x_i0 = __ldcs(&g_xg[xb]);
        float x_f0 = __ldcs(&g_xg[xb + HH]);
        float x_c0 = __ldcs(&g_xg[xb + 2*(size_t)HH]);
        float x_o0 = __ldcs(&g_xg[xb + 3*(size_t)HH]);
        float x_i1 = __ldcs(&g_xg[xb + 1]);
        float x_f1 = __ldcs(&g_xg[xb + 1 + HH]);
        float x_c1 = __ldcs(&g_xg[xb + 1 + 2*(size_t)HH]);
        float x_o1 = __ldcs(&g_xg[xb + 1 + 3*(size_t)HH]);

        float acc[2][4][4];
#pragma unroll
        for (int mt = 0; mt < 2; mt++)
#pragma unroll
            for (int nt = 0; nt < 4; nt++)
#pragma unroll
                for (int e = 0; e < 4; e++) acc[mt][nt][e] = 0.f;

        const __nv_bfloat16* hp0 = g_hv[rb][0] + (size_t)gmRow*HH + kq*256;
        const __nv_bfloat16* hp1 = g_hv[rb][1] + (size_t)gmRow*HH + kq*256;

        uint4 pf0[4], pf1[4];
        // prologue: chunk 0 -> buf 0 directly
#pragma unroll
        for (int q = 0; q < 4; q++) {
            pf0[q] = __ldcg((const uint4*)(hp0 + q*8));
            pf1[q] = __ldcg((const uint4*)(hp1 + q*8));
        }
        {
            char* d0 = sm + SM_A + w*A_WARP + 0*A_BUF + 0*A_TERM + lane*80;
            char* d1 = sm + SM_A + w*A_WARP + 0*A_BUF + 1*A_TERM + lane*80;
#pragma unroll
            for (int q = 0; q < 4; q++) {
                *(uint4*)(d0 + q*16) = pf0[q];
                *(uint4*)(d1 + q*16) = pf1[q];
            }
        }
        // prefetch chunk 1
#pragma unroll
        for (int q = 0; q < 4; q++) {
            pf0[q] = __ldcg((const uint4*)(hp0 + 32 + q*8));
            pf1[q] = __ldcg((const uint4*)(hp1 + 32 + q*8));
        }
        __syncwarp();

        for (int cc = 0; cc < 8; cc++) {
            const int buf = cc & 1;
            const uint32_t a0base = aW + buf*A_BUF + lmoff;           // term 0
            const uint32_t a1base = a0base + A_TERM;                  // term 1
            const uint32_t kbyte = (uint32_t)(kq*512 + cc*64);        // k offset into W rows (bytes)
#pragma unroll
            for (int ks = 0; ks < 2; ks++) {
                uint32_t A0[2][4], A1[2][4];
#pragma unroll
                for (int mt = 0; mt < 2; mt++) {
                    ldm4(A0[mt], a0base + mt*1280 + ks*32);
                    ldm4(A1[mt], a1base + mt*1280 + ks*32);
                }
#pragma unroll
                for (int nt = 0; nt < 4; nt++) {
                    uint32_t wb0 = smb + SM_W0 + bOff[nt] + kbyte + ks*32;
                    uint32_t wb1 = smb + SM_W1 + bOff[nt] + kbyte + ks*32;
                    uint32_t b00 = lds32(wb0), b01 = lds32(wb0 + 16);
                    uint32_t b10 = lds32(wb1), b11 = lds32(wb1 + 16);
#pragma unroll
                    for (int mt = 0; mt < 2; mt++) {
                        mma16816(acc[mt][nt], A0[mt], b00, b01);
                        mma16816(acc[mt][nt], A0[mt], b10, b11);
                        mma16816(acc[mt][nt], A1[mt], b00, b01);
                    }
                }
            }
            if (cc < 7) {
                char* d0 = sm + SM_A + w*A_WARP + (buf^1)*A_BUF + 0*A_TERM + lane*80;
                char* d1 = sm + SM_A + w*A_WARP + (buf^1)*A_BUF + 1*A_TERM + lane*80;
#pragma unroll
                for (int q = 0; q < 4; q++) {
                    *(uint4*)(d0 + q*16) = pf0[q];
                    *(uint4*)(d1 + q*16) = pf1[q];
                }
                if (cc < 6) {
#pragma unroll
                    for (int q = 0; q < 4; q++) {
                        pf0[q] = __ldcg((const uint4*)(hp0 + (cc + 2)*32 + q*8));
                        pf1[q] = __ldcg((const uint4*)(hp1 + (cc + 2)*32 + q*8));
                    }
                }
            }
            __syncwarp();
        }

        // ---- reduce K-quarters via ps[4][64][33] (aliases A region)
        __syncthreads();
        {
            float* ps = (float*)(sm + SM_A);
            const int r = lane >> 2;
            const int cn = (lane & 3) * 2;
#pragma unroll
            for (int mt = 0; mt < 2; mt++) {
#pragma unroll
                for (int nt = 0; nt < 4; nt++) {
                    int m = mh*32 + mt*16 + r;
                    int n = nt*8 + cn;
                    int i1 = (kq*64 + m)*33 + n;
                    int i2 = (kq*64 + m + 8)*33 + n;
                    ps[i1]     = acc[mt][nt][0];
                    ps[i1 + 1] = acc[mt][nt][1];
                    ps[i2]     = acc[mt][nt][2];
                    ps[i2 + 1] = acc[mt][nt][3];
                }
            }
        }
        __syncthreads();

        // ---- elementwise (2 cells per thread)
        {
            const float* ps = (const float*)(sm + SM_A);
            float s[4][2];
#pragma unroll
            for (int gt = 0; gt < 4; gt++) {
#pragma unroll
                for (int d = 0; d < 2; d++) {
                    int n = gt*8 + jl_e + d;
                    float a = 0.f;
#pragma unroll
                    for (int q = 0; q < 4; q++)
                        a += ps[(q*64 + b_e)*33 + n];
                    s[gt][d] = a;
                }
            }
            float gi0 = s[0][0] + x_i0 + bhv[0][0] + tg0;
            float gf0 = s[1][0] + x_f0 + bhv[1][0] + tg0;
            float gc0 = s[2][0] + x_c0 + bhv[2][0];
            float go0 = s[3][0] + x_o0 + bhv[3][0];
            float gi1 = s[0][1] + x_i1 + bhv[0][1] + tg1;
            float gf1 = s[1][1] + x_f1 + bhv[1][1] + tg1;
            float gc1 = s[2][1] + x_c1 + bhv[2][1];
            float go1 = s[3][1] + x_o1 + bhv[3][1];

            float ig0 = 1.f/(1.f + expf(-gi0)), fg0 = 1.f/(1.f + expf(-gf0));
            float cg0 = tanhf(gc0),             og0 = 1.f/(1.f + expf(-go0));
            float cy0 = fg0*cr0 + ig0*cg0;
            float hy0 = og0 * tanhf(cy0);
            float ig1 = 1.f/(1.f + expf(-gi1)), fg1 = 1.f/(1.f + expf(-gf1));
            float cg1 = tanhf(gc1),             og1 = 1.f/(1.f + expf(-go1));
            float cy1 = fg1*cr1 + ig1*cg1;
            float hy1 = og1 * tanhf(cy1);
            cr0 = cy0; cr1 = cy1;

            // h -> bf16 hi/lo for next step's MMA
            __nv_bfloat16 h0a = __float2bfloat16(hy0);
            __nv_bfloat16 h0b = __float2bfloat16(hy1);
            float r0 = hy0 - __bfloat162float(h0a);
            float r1 = hy1 - __bfloat162float(h0b);
            *(uint32_t*)(&g_hv[wb][0][b_e*HH + jg0]) = pack_bf2(h0a, h0b);
            *(uint32_t*)(&g_hv[wb][1][b_e*HH + jg0]) = pack_bf2(__float2bfloat16(r0), __float2bfloat16(r1));

            size_t ob = ((size_t)b_e*TT + t)*HH + jg0;
            out[ob]     = hy0;
            out[ob + 1] = hy1;
            if (t == TT - 1) {
                const size_t HN = (size_t)BB*TT*HH;
                out[HN + b_e*HH + jg0]     = hy0;
                out[HN + b_e*HH + jg0 + 1] = hy1;
                out[HN + (size_t)BB*HH + b_e*HH + jg0]     = cy0;
                out[HN + (size_t)BB*HH + b_e*HH + jg0 + 1] = cy1;
            }
        }
        if (t < TT - 1) grid_bar();
    }
}

// ----------------------------------------------------------------
extern "C" void kernel_launch(void* const* d_in, const int* in_sizes, int n_in,
                              void* d_out, int out_size) {
    const float* x     = (const float*)d_in[0];
    const float* h0    = (const float*)d_in[1];
    const float* c0    = (const float*)d_in[2];
    const float* topic = (const float*)d_in[3];
    const float* Wi    = (const float*)d_in[4];
    const float* bi    = (const float*)d_in[5];
    const float* Wh    = (const float*)d_in[6];
    const float* bh    = (const float*)d_in[7];
    const float* Wt    = (const float*)d_in[8];
    const float* bt    = (const float*)d_in[9];
    float* out = (float*)d_out;

    cudaFuncSetAttribute(k_rec, cudaFuncAttributeMaxDynamicSharedMemorySize, SM_TOTAL);

    k_xg<<<dim3(GG/128, (BB*TT)/128), 256>>>(x, Wi, bi);   // (32, 512)
    k_rec<<<NCTA, NTHR, SM_TOTAL>>>(Wh, bh, h0, c0, topic, Wt, bt, out);
}